// round 13
// baseline (speedup 1.0000x reference)
#include <cuda_runtime.h>
#include <math_constants.h>

#define DIMV   64
#define KHALF  512          // folded frequencies k = 1..512
#define MAXP   32
#define MAXPTS 16384
#define KCHUNK 16           // k's per in-kernel chunk iteration (k3)
#define PTCH   32           // point-chunks (k3 grid.x)
#define KSTAGE 32           // A/B smem staging depth in k4
#define PLANE  16           // p-lanes per point / dots per row
#define K4BLKS 128          // resident blocks for k4 (j-tiles looped inside)

// ---------------- device scratch (static: no allocation allowed) ----------
// g_max_sq is NEVER reset: updated only via atomicMax with a value that is a
// pure function of the fixed inputs -> idempotent across graph replays.
// g_c/g_s ARE accumulators and are zeroed every call (in k1). g_dx/g_dy are
// plain overwrites -> idempotent.
__device__ float g_max_sq;                    // max squared row norm
__device__ float g_dx[MAXP * MAXPTS];         // [p][i] proj (x . xi_p)/|xi_p|
__device__ float g_dy[MAXPTS * PLANE];        // [j][p] proj (y . xi_p)/|xi_p|
__device__ float g_c[MAXP * KHALF];           // adjoint cos sums
__device__ float g_s[MAXP * KHALF];           // adjoint sin sums

// g[k] = w_k * kft(k) / P  — pure function, recomputed where needed (no k2).
__device__ __forceinline__ float eval_g(int k, float s2, float invP) {
    float kf = (float)k;
    float lg = 32.f * logf(CUDART_PI_F)
             + 32.f * logf(2.f * CUDART_PI_F * s2)
             - lgammaf(32.f)
             + 63.f * logf(kf)
             - 2.f * CUDART_PI_F * CUDART_PI_F * s2 * kf * kf;
    float kft = expf(lg);
    float wk  = (k < KHALF) ? 2.f : 1.f;      // symmetry weight; k=512 unpaired
    return kft * wk * invP;
}

__device__ __forceinline__ float decode_scale(const int* scale_raw) {
    int iv = *scale_raw;                       // int32 or float32 bits
    return (iv > -10000000 && iv < 10000000) ? (float)iv : __int_as_float(iv);
}

// Block-cooperative: sf and kmax from g_max_sq + scale. Needs all 256 threads.
__device__ __forceinline__ void block_sf_kmax(const int* scale_raw, int P,
                                              float& sf, float& s2, float& invP,
                                              int& kmax, int* skmax) {
    sf   = 0.3f / sqrtf(g_max_sq);
    float s = decode_scale(scale_raw) * sf;
    s2   = s * s;
    invP = 1.0f / (float)P;
    if (threadIdx.x == 0) *skmax = 0;
    __syncthreads();
    int local = 0;
    for (int k = threadIdx.x + 1; k <= KHALF; k += 256)
        if (eval_g(k, s2, invP) > 0.f) local = k;   // k increasing across strides
    if (local) atomicMax(skmax, local);
    __syncthreads();
    kmax = *skmax;
}

// ---------------- kernel 1: zero accums + row-norm max + ALL projections --
// 4 threads per row (16 dims each); partial dots combined via shfl_xor.
__global__ void __launch_bounds__(256) k1(const float* __restrict__ x,
                                          const float* __restrict__ y,
                                          const float* __restrict__ xis,
                                          int N, int M, int P) {
    __shared__ float sxi[PLANE][DIMV];
    __shared__ float sinv[PLANE];
    for (int i = threadIdx.x; i < PLANE * DIMV; i += blockDim.x) {
        int p = i >> 6, dd = i & 63;
        sxi[p][dd] = (p < P) ? xis[p * DIMV + dd] : 0.f;
    }
    __syncthreads();
    if (threadIdx.x < PLANE) {
        int p = threadIdx.x;
        float ss = 0.f;
        #pragma unroll 16
        for (int dd = 0; dd < DIMV; dd++) ss = fmaf(sxi[p][dd], sxi[p][dd], ss);
        sinv[p] = (p < P) ? 1.0f / sqrtf(ss) : 0.f;
    }
    __syncthreads();

    int tid = blockIdx.x * blockDim.x + threadIdx.x;
    if (tid < MAXP * KHALF) { g_c[tid] = 0.f; g_s[tid] = 0.f; }

    int r  = tid >> 2;            // row
    int qt = tid & 3;             // quarter of the row (16 dims)
    float v = 0.f;
    if (r < N + M) {
        const float* row = (r < N) ? x + (size_t)r * DIMV
                                   : y + (size_t)(r - N) * DIMV;
        const float4* r4 = (const float4*)(row + qt * (DIMV / 4));
        float d[PLANE];
        #pragma unroll
        for (int p = 0; p < PLANE; p++) d[p] = 0.f;
        float ss = 0.f;
        #pragma unroll
        for (int q = 0; q < DIMV / 16; q++) {         // 4 float4 per thread
            float4 t = r4[q];
            int b = qt * (DIMV / 4) + 4 * q;
            ss = fmaf(t.x, t.x, ss); ss = fmaf(t.y, t.y, ss);
            ss = fmaf(t.z, t.z, ss); ss = fmaf(t.w, t.w, ss);
            #pragma unroll
            for (int p = 0; p < PLANE; p++) {
                d[p] = fmaf(t.x, sxi[p][b],   d[p]);
                d[p] = fmaf(t.y, sxi[p][b+1], d[p]);
                d[p] = fmaf(t.z, sxi[p][b+2], d[p]);
                d[p] = fmaf(t.w, sxi[p][b+3], d[p]);
            }
        }
        // combine the 4 quarter-partials (lanes qt=0..3 of this row)
        #pragma unroll
        for (int p = 0; p < PLANE; p++) {
            d[p] += __shfl_xor_sync(0xffffffffu, d[p], 1);
            d[p] += __shfl_xor_sync(0xffffffffu, d[p], 2);
        }
        ss += __shfl_xor_sync(0xffffffffu, ss, 1);
        ss += __shfl_xor_sync(0xffffffffu, ss, 2);
        v = ss;
        if (qt == 0) {
            if (r < N) {
                #pragma unroll
                for (int p = 0; p < PLANE; p++)
                    if (p < P) g_dx[p * N + r] = d[p] * sinv[p];
            } else {
                int j = r - N;
                #pragma unroll
                for (int p = 0; p < PLANE; p++)
                    if (p < P) g_dy[j * PLANE + p] = d[p] * sinv[p];
            }
        }
    }
    #pragma unroll
    for (int o = 16; o; o >>= 1) v = fmaxf(v, __shfl_down_sync(0xffffffffu, v, o));
    __shared__ float sm[8];
    if ((threadIdx.x & 31) == 0) sm[threadIdx.x >> 5] = v;
    __syncthreads();
    if (threadIdx.x < 8) {
        v = sm[threadIdx.x];
        #pragma unroll
        for (int o = 4; o; o >>= 1) v = fmaxf(v, __shfl_down_sync(0xffu, v, o));
        if (threadIdx.x == 0)
            atomicMax((int*)&g_max_sq, __float_as_int(v));  // non-negative floats: int-order ok
    }
}

// ---------------- kernel 3: adjoint trig sums (projections precomputed) ---
// grid (PTCH, P). sf/kmax computed block-locally (k2 eliminated).
__global__ void __launch_bounds__(256) k3(const float* __restrict__ w,
                                          const int* __restrict__ scl,
                                          int N, int P) {
    __shared__ int skmax;
    float sf, s2, invP; int kmax;
    block_sf_kmax(scl, P, sf, s2, invP, kmax, &skmax);

    int p = blockIdx.y;
    float sf2pi = 2.f * CUDART_PI_F * sf;
    int chunk = (N + PTCH - 1) / PTCH;
    int i0 = blockIdx.x * chunk;
    int i1 = min(N, i0 + chunk);
    int lane = threadIdx.x & 31, wid = threadIdx.x >> 5;
    const float* dx = g_dx + (size_t)p * N;
    __shared__ float red[8][2 * KCHUNK];

    for (int k0 = 1; k0 <= kmax; k0 += KCHUNK) {
        float ac[KCHUNK], as_[KCHUNK];
        #pragma unroll
        for (int j = 0; j < KCHUNK; j++) { ac[j] = 0.f; as_[j] = 0.f; }
        for (int i = i0 + threadIdx.x; i < i1; i += blockDim.x) {
            float th = sf2pi * dx[i];
            float wt = w[i];
            float st, ct; sincosf(th, &st, &ct);          // rotation step
            float sk, ck;
            if (k0 == 1) { ck = ct; sk = st; }            // common case: skip 2nd sincos
            else         sincosf((float)k0 * th, &sk, &ck);
            #pragma unroll
            for (int j = 0; j < KCHUNK; j++) {
                ac[j]  = fmaf(wt, ck, ac[j]);
                as_[j] = fmaf(wt, sk, as_[j]);
                float nc = fmaf(ck, ct, -sk * st);
                float ns = fmaf(sk, ct,  ck * st);
                ck = nc; sk = ns;
            }
        }
        #pragma unroll
        for (int j = 0; j < KCHUNK; j++) {
            float vc = ac[j], vs = as_[j];
            #pragma unroll
            for (int o = 16; o; o >>= 1) {
                vc += __shfl_down_sync(0xffffffffu, vc, o);
                vs += __shfl_down_sync(0xffffffffu, vs, o);
            }
            if (lane == 0) { red[wid][j] = vc; red[wid][KCHUNK + j] = vs; }
        }
        __syncthreads();
        for (int t = threadIdx.x; t < 2 * KCHUNK; t += blockDim.x) {
            float tot = 0.f;
            #pragma unroll
            for (int wdx = 0; wdx < 8; wdx++) tot += red[wdx][t];
            int k = k0 + (t & (KCHUNK - 1));
            if (k <= kmax) {
                float* dst = (t < KCHUNK) ? g_c : g_s;
                atomicAdd(&dst[p * KHALF + (k - 1)], tot);
            }
        }
        __syncthreads();   // red[] reused next chunk iteration
    }
}

// ---------------- kernel 4: forward NDFT (projections precomputed) --------
// K4BLKS resident blocks; each loops over j-tiles (16 points x 16 p-lanes).
// sf/kmax/g[k] computed block-locally; staging amortized across tiles.
__global__ void __launch_bounds__(256) k4(const int* __restrict__ scl,
                                          float* __restrict__ out, int M, int P) {
    __shared__ int skmax;
    float sf, s2, invP; int kmax;
    block_sf_kmax(scl, P, sf, s2, invP, kmax, &skmax);

    __shared__ float sAc[KSTAGE][MAXP];           // transposed: lane p -> bank p
    __shared__ float sAs[KSTAGE][MAXP];
    int kst = min(kmax, KSTAGE);
    for (int i = threadIdx.x; i < P * kst; i += blockDim.x) {
        int p = i / kst, k = (i % kst) + 1;
        float g = eval_g(k, s2, invP);
        sAc[k - 1][p] = g * g_c[p * KHALF + k - 1];
        sAs[k - 1][p] = g * g_s[p * KHALF + k - 1];
    }
    __syncthreads();

    float sf2pi = 2.f * CUDART_PI_F * sf;
    int sub = threadIdx.x & 15;           // slice lane
    int pt  = threadIdx.x >> 4;           // point within tile
    int ntile = (M + 15) / 16;
    for (int tile = blockIdx.x; tile < ntile; tile += gridDim.x) {
        int j = tile * 16 + pt;
        float acc = 0.f;
        if (j < M) {
            for (int p = sub; p < P; p += 16) {
                float th = sf2pi * g_dy[j * PLANE + p];   // 64B-contiguous across lanes
                float st, ct; sincosf(th, &st, &ct);
                float ck = ct, sk = st;
                for (int k = 0; k < kst; k++) {
                    acc = fmaf(sAc[k][p], ck, acc);
                    acc = fmaf(sAs[k][p], sk, acc);
                    float nc = fmaf(ck, ct, -sk * st);
                    float ns = fmaf(sk, ct,  ck * st);
                    ck = nc; sk = ns;
                }
                for (int k = kst + 1; k <= kmax; k++) {   // rare tail (kmax > KSTAGE)
                    float g = eval_g(k, s2, invP);
                    acc = fmaf(g * g_c[p * KHALF + k - 1], ck, acc);
                    acc = fmaf(g * g_s[p * KHALF + k - 1], sk, acc);
                    float nc = fmaf(ck, ct, -sk * st);
                    float ns = fmaf(sk, ct,  ck * st);
                    ck = nc; sk = ns;
                }
            }
        }
        #pragma unroll
        for (int o = 8; o; o >>= 1)
            acc += __shfl_down_sync(0xffffffffu, acc, o, 16);  // reduce 16-lane group
        if (sub == 0 && j < M) out[j] = acc;   // w_k and 1/P folded into g[k]
    }
}

// ---------------- launch ---------------------------------------------------
extern "C" void kernel_launch(void* const* d_in, const int* in_sizes, int n_in,
                              void* d_out, int out_size) {
    const float* x   = (const float*)d_in[0];
    const float* y   = (const float*)d_in[1];
    const float* w   = (const float*)d_in[2];
    const float* xis = (const float*)d_in[3];
    const int*   scl = (const int*)d_in[4];
    int N = in_sizes[0] / DIMV;
    int M = in_sizes[1] / DIMV;
    int P = in_sizes[3] / DIMV;

    int n1 = max((N + M) * 4, MAXP * KHALF);
    k1<<<(n1 + 255) / 256, 256>>>(x, y, xis, N, M, P);
    dim3 gc(PTCH, P);
    k3<<<gc, 256>>>(w, scl, N, P);
    k4<<<K4BLKS, 256>>>(scl, (float*)d_out, M, P);
}